// round 12
// baseline (speedup 1.0000x reference)
#include <cuda_runtime.h>
#include <cuda_fp16.h>
#include <cstdint>

#define NCHUNK 105
#define HID    512
#define NROWS  220000
#define KD     512

// ---- big GEMM ----
#define MT     256            // rows per CTA (8 M-warp-groups x m32)
#define NTILES 7              // n8 tiles per warp (2 N groups x 56 = 112)
#define KSTEPS 32             // k16 steps
#define BSROW  480            // bytes per Bs row (448 used + 32 pad)
#define BS_SMEM (256 * BSROW) // 122880

// ---------------- device scratch ----------------
__device__ __half g_Bp[256 * 224];      // permuted fp16 B image

// ---------------- PTX helpers ----------------
__device__ __forceinline__ uint32_t smem_u32_of(const void* p) {
    uint32_t a;
    asm("{ .reg .u64 t; cvta.to.shared.u64 t, %1; cvt.u32.u64 %0, t; }" : "=r"(a) : "l"(p));
    return a;
}
__device__ __forceinline__ void mma16816(float* d, const uint32_t* a, const uint32_t* b) {
    asm volatile(
        "mma.sync.aligned.m16n8k16.row.col.f32.f16.f16.f32 "
        "{%0,%1,%2,%3}, {%4,%5,%6,%7}, {%8,%9}, {%0,%1,%2,%3};"
        : "+f"(d[0]), "+f"(d[1]), "+f"(d[2]), "+f"(d[3])
        : "r"(a[0]), "r"(a[1]), "r"(a[2]), "r"(a[3]), "r"(b[0]), "r"(b[1]));
}
__device__ __forceinline__ uint32_t cvt2(float lo, float hi) {
    __half2 h = __floats2half2_rn(lo, hi);
    return *reinterpret_cast<uint32_t*>(&h);
}
__device__ __forceinline__ uint32_t ldsb32(uint32_t addr) {
    uint32_t v;
    asm volatile("ld.shared.b32 %0, [%1];" : "=r"(v) : "r"(addr));
    return v;
}
__device__ __forceinline__ float dot4(float4 a, float4 b) {
    return a.x * b.x + a.y * b.y + a.z * b.z + a.w * b.w;
}

// ---------------- fused MLP: all 3 layers, chunk-parallel ---------------
// 35 blocks x 512 thr; block owns 3 chunks; h1/h2 in SMEM (no grid sync
// needed: MLP rows are independent). Warp computes 32 j per layer via
// coalesced W-row loads + shfl reduce. Layer-3 writes permuted B image.
__global__ __launch_bounds__(512)
void mlp_all_kernel(const float* __restrict__ preference,
                    const float* __restrict__ pref_emb,
                    const float* __restrict__ chunk_emb,
                    const float* __restrict__ W1, const float* __restrict__ b1,
                    const float* __restrict__ W2, const float* __restrict__ b2,
                    const float* __restrict__ W3, const float* __restrict__ b3) {
    __shared__ float xs [3][128];
    __shared__ float h1s[3][512];
    __shared__ float h2s[3][512];
    __shared__ float pe[64];

    const int tid = threadIdx.x, lane = tid & 31, warp = tid >> 5;
    const int cb = blockIdx.x * 3;

    if (tid < 64)
        pe[tid] = preference[0] * pref_emb[tid] + preference[1] * pref_emb[64 + tid];
    __syncthreads();
    for (int i = tid; i < 3 * 128; i += 512) {
        int c = i >> 7, k = i & 127;
        xs[c][k] = (k < 64) ? pe[k] : chunk_emb[(cb + c) * 64 + (k - 64)];
    }
    __syncthreads();

    // ---- layer 1: in=128 ----
    for (int jj = 0; jj < 32; jj++) {
        int j = warp * 32 + jj;
        float4 w = reinterpret_cast<const float4*>(W1)[j * 32 + lane];
        float v[3];
#pragma unroll
        for (int c = 0; c < 3; c++)
            v[c] = dot4(w, reinterpret_cast<const float4*>(xs[c])[lane]);
#pragma unroll
        for (int c = 0; c < 3; c++) {
#pragma unroll
            for (int o = 16; o; o >>= 1) v[c] += __shfl_down_sync(~0u, v[c], o);
        }
        if (lane == 0) {
            float bj = b1[j];
#pragma unroll
            for (int c = 0; c < 3; c++) h1s[c][j] = fmaxf(v[c] + bj, 0.f);
        }
    }
    __syncthreads();

    // ---- layer 2: in=512 ----
    for (int jj = 0; jj < 32; jj++) {
        int j = warp * 32 + jj;
        float v[3] = {0.f, 0.f, 0.f};
#pragma unroll
        for (int i = 0; i < 4; i++) {
            float4 w = reinterpret_cast<const float4*>(W2)[j * 128 + i * 32 + lane];
#pragma unroll
            for (int c = 0; c < 3; c++)
                v[c] += dot4(w, reinterpret_cast<const float4*>(h1s[c])[i * 32 + lane]);
        }
#pragma unroll
        for (int c = 0; c < 3; c++) {
#pragma unroll
            for (int o = 16; o; o >>= 1) v[c] += __shfl_down_sync(~0u, v[c], o);
        }
        if (lane == 0) {
            float bj = b2[j];
#pragma unroll
            for (int c = 0; c < 3; c++) h2s[c][j] = fmaxf(v[c] + bj, 0.f);
        }
    }
    __syncthreads();

    // ---- layer 3: in=512, no relu -> permuted fp16 B image ----
    for (int jj = 0; jj < 32; jj++) {
        int j = warp * 32 + jj;
        float v[3] = {0.f, 0.f, 0.f};
#pragma unroll
        for (int i = 0; i < 4; i++) {
            float4 w = reinterpret_cast<const float4*>(W3)[j * 128 + i * 32 + lane];
#pragma unroll
            for (int c = 0; c < 3; c++)
                v[c] += dot4(w, reinterpret_cast<const float4*>(h2s[c])[i * 32 + lane]);
        }
#pragma unroll
        for (int c = 0; c < 3; c++) {
#pragma unroll
            for (int o = 16; o; o >>= 1) v[c] += __shfl_down_sync(~0u, v[c], o);
        }
        if (lane == 0) {
            float bj = b3[j];
            int aa   = j & 15;
            int row  = (j >> 4) * 8 + (aa >> 2) + 4 * ((aa >> 1) & 1);
            int bsel = aa & 1;
#pragma unroll
            for (int c = 0; c < 3; c++)
                g_Bp[row * 224 + (cb + c) * 2 + bsel] = __float2half_rn(v[c] + bj);
        }
    }
}

// ---------------- big GEMM: out[n][m] = ws[m] . rep[n] -------------------
// 512 thr (16 warps: 8 in M x 2 in N), warp tile m32 x n56.
// A direct-LDG (k-permuted), B image resident in SMEM. No mainloop syncs.
__global__ __launch_bounds__(512, 1)
void big_kernel(const float* __restrict__ ws, float* __restrict__ out) {
    extern __shared__ char smem[];
    const uint32_t sb = smem_u32_of(smem);
    const int tid = threadIdx.x, lane = tid & 31, wid = tid >> 5;
    const int wm = wid & 7;          // M group (8)
    const int wn = wid >> 3;         // N group (2)

    // load permuted B image (256 rows x 224 halves) with 480B row stride
    {
        const float4* src = reinterpret_cast<const float4*>(g_Bp);
        for (int i = tid; i < 256 * 28; i += 512) {
            int r = i / 28, q = i - r * 28;
            *reinterpret_cast<float4*>(smem + r * BSROW + q * 16) = src[i];
        }
    }
    __syncthreads();

    const int g = lane >> 2, q = lane & 3;
    const long long mwbase = (long long)blockIdx.x * MT + wm * 32;

    // 4 A-row pointers (rows g, g+8, g+16, g+24 of the warp's m32 block)
    const float4* ap[4];
#pragma unroll
    for (int j = 0; j < 4; j++) {
        long long r = mwbase + g + 8 * j;
        if (r >= NROWS) r = NROWS - 1;
        ap[j] = reinterpret_cast<const float4*>(ws) + r * (KD / 4) + q;
    }

    // b-frag base; this warp's N window starts at tile wn*7
    const uint32_t bbase = sb + (uint32_t)(lane & 3) * BSROW +
                           (uint32_t)(lane >> 2) * 4 + (uint32_t)wn * (7 * 32);

    float acc[2][NTILES][4];
#pragma unroll
    for (int a = 0; a < 2; a++)
#pragma unroll
        for (int b = 0; b < NTILES; b++)
#pragma unroll
            for (int c = 0; c < 4; c++) acc[a][b][c] = 0.f;

    // 2-deep A prefetch
    float4 pa[4][2];
#pragma unroll
    for (int j = 0; j < 4; j++) {
        pa[j][0] = ap[j][0];
        pa[j][1] = ap[j][4];
    }

#pragma unroll 2
    for (int t = 0; t < KSTEPS; t++) {
        float4 ca[4];
#pragma unroll
        for (int j = 0; j < 4; j++) {
            ca[j] = pa[j][t & 1];
            if (t + 2 < KSTEPS) pa[j][t & 1] = ap[j][(t + 2) * 4];
        }
        uint32_t ar[2][4];
        ar[0][0] = cvt2(ca[0].x, ca[0].y);
        ar[0][1] = cvt2(ca[1].x, ca[1].y);
        ar[0][2] = cvt2(ca[0].z, ca[0].w);
        ar[0][3] = cvt2(ca[1].z, ca[1].w);
        ar[1][0] = cvt2(ca[2].x, ca[2].y);
        ar[1][1] = cvt2(ca[3].x, ca[3].y);
        ar[1][2] = cvt2(ca[2].z, ca[2].w);
        ar[1][3] = cvt2(ca[3].z, ca[3].w);

        uint32_t brow = bbase + (uint32_t)t * (8 * BSROW);
#pragma unroll
        for (int nt = 0; nt < NTILES; nt++) {
            uint32_t bfr[2];
            bfr[0] = ldsb32(brow + nt * 32);
            bfr[1] = ldsb32(brow + 4 * BSROW + nt * 32);
            mma16816(acc[0][nt], ar[0], bfr);
            mma16816(acc[1][nt], ar[1], bfr);
        }
    }

    // ---- epilogue ----
#pragma unroll
    for (int tm = 0; tm < 2; tm++) {
        long long m0 = mwbase + tm * 16 + g;
        long long m1 = m0 + 8;
        int nb = 2 * q;
#pragma unroll
        for (int nt = 0; nt < NTILES; nt++) {
            int n0 = (wn * 7 + nt) * 8 + nb, n1 = n0 + 1;
            const float* c = acc[tm][nt];
            if (m0 < NROWS) {
                if (n0 < NCHUNK) out[(size_t)n0 * NROWS + m0] = c[0];
                if (n1 < NCHUNK) out[(size_t)n1 * NROWS + m0] = c[1];
            }
            if (m1 < NROWS) {
                if (n0 < NCHUNK) out[(size_t)n0 * NROWS + m1] = c[2];
                if (n1 < NCHUNK) out[(size_t)n1 * NROWS + m1] = c[3];
            }
        }
    }
}

// ---------------------------- launcher -----------------------------------
extern "C" void kernel_launch(void* const* d_in, const int* in_sizes, int n_in,
                              void* d_out, int out_size) {
    const float* preference = (const float*)d_in[0];
    const float* pref_emb   = (const float*)d_in[1];
    const float* chunk_emb  = (const float*)d_in[2];
    const float* W1         = (const float*)d_in[3];
    const float* b1         = (const float*)d_in[4];
    const float* W2         = (const float*)d_in[5];
    const float* b2         = (const float*)d_in[6];
    const float* W3         = (const float*)d_in[7];
    const float* b3         = (const float*)d_in[8];
    const float* ws         = (const float*)d_in[9];
    float* out = (float*)d_out;

    static int attr_done = 0;
    if (!attr_done) {
        cudaFuncSetAttribute(big_kernel,
            cudaFuncAttributeMaxDynamicSharedMemorySize, BS_SMEM);
        attr_done = 1;
    }

    mlp_all_kernel<<<35, 512>>>(preference, pref_emb, chunk_emb,
                                W1, b1, W2, b2, W3, b3);

    int nblocks = (NROWS + MT - 1) / MT;   // 860
    big_kernel<<<nblocks, 512, BS_SMEM>>>(ws, out);
}

// round 13
// speedup vs baseline: 1.5603x; 1.5603x over previous
#include <cuda_runtime.h>
#include <cuda_fp16.h>
#include <cstdint>

#define NCHUNK 105
#define HID    512
#define IND1   128
#define NROWS  220000
#define KD     512

// ---- big GEMM ----
#define MT     256            // rows per CTA (8 warps x m32)
#define NTILES 14             // n8 tiles (112 cols, 105 used)
#define KSTEPS 32             // k16 steps
#define BSROW  480            // bytes per Bs row (448 used + 32 pad) -> conflict-free
#define BS_SMEM (256 * BSROW) // 122880

// ---------------- device scratch ----------------
__device__ float  g_x  [NCHUNK * IND1];
__device__ float  g_h1 [NCHUNK * HID];
__device__ float  g_h2 [NCHUNK * HID];
__device__ __half g_Bp [256 * 224];     // permuted fp16 B image

// ---------------- PTX helpers ----------------
__device__ __forceinline__ uint32_t smem_u32_of(const void* p) {
    uint32_t a;
    asm("{ .reg .u64 t; cvta.to.shared.u64 t, %1; cvt.u32.u64 %0, t; }" : "=r"(a) : "l"(p));
    return a;
}
__device__ __forceinline__ void mma16816(float* d, const uint32_t* a, const uint32_t* b) {
    asm volatile(
        "mma.sync.aligned.m16n8k16.row.col.f32.f16.f16.f32 "
        "{%0,%1,%2,%3}, {%4,%5,%6,%7}, {%8,%9}, {%0,%1,%2,%3};"
        : "+f"(d[0]), "+f"(d[1]), "+f"(d[2]), "+f"(d[3])
        : "r"(a[0]), "r"(a[1]), "r"(a[2]), "r"(a[3]), "r"(b[0]), "r"(b[1]));
}
__device__ __forceinline__ uint32_t cvt2(float lo, float hi) {
    __half2 h = __floats2half2_rn(lo, hi);
    return *reinterpret_cast<uint32_t*>(&h);
}
__device__ __forceinline__ uint32_t ldsb32(uint32_t addr) {
    uint32_t v;
    asm volatile("ld.shared.b32 %0, [%1];" : "=r"(v) : "r"(addr));
    return v;
}

// ---------------- build x = [pref_embedding | chunk_emb] -----------------
__global__ __launch_bounds__(256)
void build_x_kernel(const float* __restrict__ preference,
                    const float* __restrict__ pref_emb,
                    const float* __restrict__ chunk_emb) {
    __shared__ float pe[64];
    int tid = threadIdx.x;
    if (tid < 64)
        pe[tid] = preference[0] * pref_emb[tid] + preference[1] * pref_emb[64 + tid];
    __syncthreads();
    for (int i = tid; i < NCHUNK * IND1; i += blockDim.x) {
        int c = i >> 7, k = i & 127;
        g_x[i] = (k < 64) ? pe[k] : chunk_emb[c * 64 + (k - 64)];
    }
}

// ---------------- MLP layer (proven R5 structure) ------------------------
// EMITB: layer-3 epilogue writes permuted fp16 B image for the big GEMM.
template <int IND, bool RELU, bool EMITB>
__global__ __launch_bounds__(512)
void layer_kernel(const float* __restrict__ in, const float* __restrict__ W,
                  const float* __restrict__ bias, float* __restrict__ out) {
    constexpr int JITER = 2;
    constexpr int Q = IND / 4;
    __shared__ float4 in_s[8][Q];

    int tid = threadIdx.x, lane = tid & 31, warp = tid >> 5;
    int cbase = blockIdx.y * 8;

    for (int i = tid; i < 8 * Q; i += 512) {
        int c = i / Q, q = i % Q;
        float4 v = make_float4(0.f, 0.f, 0.f, 0.f);
        if (cbase + c < NCHUNK)
            v = reinterpret_cast<const float4*>(in)[(cbase + c) * Q + q];
        in_s[c][q] = v;
    }
    __syncthreads();

    for (int t = 0; t < JITER; t++) {
        int j = blockIdx.x * (16 * JITER) + warp * JITER + t;
        float acc[8];
#pragma unroll
        for (int c = 0; c < 8; c++) acc[c] = 0.f;
        const float4* Wr = reinterpret_cast<const float4*>(W) + (size_t)j * Q;
        for (int i = lane; i < Q; i += 32) {
            float4 w = Wr[i];
#pragma unroll
            for (int c = 0; c < 8; c++) {
                float4 x = in_s[c][i];
                acc[c] += w.x * x.x + w.y * x.y + w.z * x.z + w.w * x.w;
            }
        }
        // permutation for B image: j = 16t' + aa, aa = 4q + 2h + b
        int aa   = j & 15;
        int row  = (j >> 4) * 8 + (aa >> 2) + 4 * ((aa >> 1) & 1);
        int bsel = aa & 1;
#pragma unroll
        for (int c = 0; c < 8; c++) {
            float v = acc[c];
#pragma unroll
            for (int off = 16; off; off >>= 1) v += __shfl_down_sync(~0u, v, off);
            if (lane == 0 && (cbase + c) < NCHUNK) {
                v += bias[j];
                if (RELU) v = fmaxf(v, 0.f);
                if (EMITB)
                    g_Bp[row * 224 + (cbase + c) * 2 + bsel] = __float2half_rn(v);
                else
                    out[(cbase + c) * HID + j] = v;
            }
        }
    }
}

// ---------------- big GEMM: out[n][m] = ws[m] . rep[n] -------------------
// 256 thr (8 warps), warp tile m32 x n112, A direct-LDG (k-permuted),
// B image resident in SMEM. No mainloop syncs. 4-deep A prefetch.
__global__ __launch_bounds__(256, 1)
void big_kernel(const float* __restrict__ ws, float* __restrict__ out) {
    extern __shared__ char smem[];
    const uint32_t sb = smem_u32_of(smem);
    const int tid = threadIdx.x, lane = tid & 31, wid = tid >> 5;

    // load permuted B image (256 rows x 224 halves) with 480B row stride
    {
        const float4* src = reinterpret_cast<const float4*>(g_Bp);
        for (int i = tid; i < 256 * 28; i += 256) {
            int r = i / 28, q = i - r * 28;
            *reinterpret_cast<float4*>(smem + r * BSROW + q * 16) = src[i];
        }
    }
    __syncthreads();

    const int g = lane >> 2, q = lane & 3;
    const long long mwbase = (long long)blockIdx.x * MT + wid * 32;

    // 4 A-row pointers (rows g, g+8, g+16, g+24 of the warp's m32 block)
    const float4* ap[4];
#pragma unroll
    for (int j = 0; j < 4; j++) {
        long long r = mwbase + g + 8 * j;
        if (r >= NROWS) r = NROWS - 1;
        ap[j] = reinterpret_cast<const float4*>(ws) + r * (KD / 4) + q;
    }

    // b-frag base (R6-proven pattern)
    const uint32_t bbase = sb + (uint32_t)(lane & 3) * BSROW + (uint32_t)(lane >> 2) * 4;

    float acc[2][NTILES][4];
#pragma unroll
    for (int a = 0; a < 2; a++)
#pragma unroll
        for (int b = 0; b < NTILES; b++)
#pragma unroll
            for (int c = 0; c < 4; c++) acc[a][b][c] = 0.f;

    // 4-deep A prefetch (~600+ cyc lookahead, covers DRAM latency)
    float4 pa[4][4];
#pragma unroll
    for (int j = 0; j < 4; j++) {
#pragma unroll
        for (int d = 0; d < 4; d++) pa[j][d] = ap[j][d * 4];
    }

#pragma unroll 4
    for (int t = 0; t < KSTEPS; t++) {
        float4 ca[4];
#pragma unroll
        for (int j = 0; j < 4; j++) {
            ca[j] = pa[j][t & 3];
            if (t + 4 < KSTEPS) pa[j][t & 3] = ap[j][(t + 4) * 4];
        }
        uint32_t ar[2][4];
        // tm=0: rows g (ca0), g+8 (ca1); tm=1: rows g+16 (ca2), g+24 (ca3)
        ar[0][0] = cvt2(ca[0].x, ca[0].y);
        ar[0][1] = cvt2(ca[1].x, ca[1].y);
        ar[0][2] = cvt2(ca[0].z, ca[0].w);
        ar[0][3] = cvt2(ca[1].z, ca[1].w);
        ar[1][0] = cvt2(ca[2].x, ca[2].y);
        ar[1][1] = cvt2(ca[3].x, ca[3].y);
        ar[1][2] = cvt2(ca[2].z, ca[2].w);
        ar[1][3] = cvt2(ca[3].z, ca[3].w);

        uint32_t brow = bbase + (uint32_t)t * (8 * BSROW);
#pragma unroll
        for (int nt = 0; nt < NTILES; nt++) {
            uint32_t bfr[2];
            bfr[0] = ldsb32(brow + nt * 32);
            bfr[1] = ldsb32(brow + 4 * BSROW + nt * 32);
            mma16816(acc[0][nt], ar[0], bfr);
            mma16816(acc[1][nt], ar[1], bfr);
        }
    }

    // ---- epilogue ----
#pragma unroll
    for (int tm = 0; tm < 2; tm++) {
        long long m0 = mwbase + tm * 16 + g;
        long long m1 = m0 + 8;
        int nb = 2 * q;
#pragma unroll
        for (int nt = 0; nt < NTILES; nt++) {
            int n0 = nt * 8 + nb, n1 = n0 + 1;
            const float* c = acc[tm][nt];
            if (m0 < NROWS) {
                if (n0 < NCHUNK) out[(size_t)n0 * NROWS + m0] = c[0];
                if (n1 < NCHUNK) out[(size_t)n1 * NROWS + m0] = c[1];
            }
            if (m1 < NROWS) {
                if (n0 < NCHUNK) out[(size_t)n0 * NROWS + m1] = c[2];
                if (n1 < NCHUNK) out[(size_t)n1 * NROWS + m1] = c[3];
            }
        }
    }
}

// ---------------------------- launcher -----------------------------------
extern "C" void kernel_launch(void* const* d_in, const int* in_sizes, int n_in,
                              void* d_out, int out_size) {
    const float* preference = (const float*)d_in[0];
    const float* pref_emb   = (const float*)d_in[1];
    const float* chunk_emb  = (const float*)d_in[2];
    const float* W1         = (const float*)d_in[3];
    const float* b1         = (const float*)d_in[4];
    const float* W2         = (const float*)d_in[5];
    const float* b2         = (const float*)d_in[6];
    const float* W3         = (const float*)d_in[7];
    const float* b3         = (const float*)d_in[8];
    const float* ws         = (const float*)d_in[9];
    float* out = (float*)d_out;

    float *px, *ph1, *ph2;
    cudaGetSymbolAddress((void**)&px,  g_x);
    cudaGetSymbolAddress((void**)&ph1, g_h1);
    cudaGetSymbolAddress((void**)&ph2, g_h2);

    static int attr_done = 0;
    if (!attr_done) {
        cudaFuncSetAttribute(big_kernel,
            cudaFuncAttributeMaxDynamicSharedMemorySize, BS_SMEM);
        attr_done = 1;
    }

    build_x_kernel<<<1, 256>>>(preference, pref_emb, chunk_emb);

    dim3 lgrid(HID / 32, (NCHUNK + 7) / 8);  // 16 x 14
    layer_kernel<IND1, true,  false><<<lgrid, 512>>>(px,  W1, b1, ph1);
    layer_kernel<HID,  true,  false><<<lgrid, 512>>>(ph1, W2, b2, ph2);
    layer_kernel<HID,  false, true ><<<lgrid, 512>>>(ph2, W3, b3, ph2 /*unused*/);

    int nblocks = (NROWS + MT - 1) / MT;   // 860
    big_kernel<<<nblocks, 256, BS_SMEM>>>(ws, out);
}

// round 15
// speedup vs baseline: 1.6882x; 1.0820x over previous
#include <cuda_runtime.h>
#include <cuda_fp16.h>
#include <cstdint>

#define NCHUNK 105
#define HID    512
#define IND1   128
#define NROWS  220000
#define KD     512

// ---- big GEMM ----
#define MT     256            // rows per CTA (8 warps x m32)
#define NTILES 14             // n8 tiles (112 cols, 105 used)
#define KSTEPS 32             // k16 steps
#define BSROW  480            // bytes per Bs row (448 used + 32 pad) -> conflict-free
#define BS_SMEM (256 * BSROW) // 122880

// ---------------- device scratch ----------------
__device__ float  g_h1 [NCHUNK * HID];
__device__ float  g_h2 [NCHUNK * HID];
__device__ __half g_Bp [256 * 224];     // permuted fp16 B image

// ---------------- PTX helpers ----------------
__device__ __forceinline__ uint32_t smem_u32_of(const void* p) {
    uint32_t a;
    asm("{ .reg .u64 t; cvta.to.shared.u64 t, %1; cvt.u32.u64 %0, t; }" : "=r"(a) : "l"(p));
    return a;
}
__device__ __forceinline__ void mma16816(float* d, const uint32_t* a, const uint32_t* b) {
    asm volatile(
        "mma.sync.aligned.m16n8k16.row.col.f32.f16.f16.f32 "
        "{%0,%1,%2,%3}, {%4,%5,%6,%7}, {%8,%9}, {%0,%1,%2,%3};"
        : "+f"(d[0]), "+f"(d[1]), "+f"(d[2]), "+f"(d[3])
        : "r"(a[0]), "r"(a[1]), "r"(a[2]), "r"(a[3]), "r"(b[0]), "r"(b[1]));
}
__device__ __forceinline__ uint32_t cvt2(float lo, float hi) {
    __half2 h = __floats2half2_rn(lo, hi);
    return *reinterpret_cast<uint32_t*>(&h);
}
__device__ __forceinline__ uint32_t ldsb32(uint32_t addr) {
    uint32_t v;
    asm volatile("ld.shared.b32 %0, [%1];" : "=r"(v) : "r"(addr));
    return v;
}
__device__ __forceinline__ float dot4(float4 a, float4 b) {
    return a.x * b.x + a.y * b.y + a.z * b.z + a.w * b.w;
}

// ---------------- MLP layer ------------------------
// Warp computes 2 outputs j (interleaved in the k-loop: 8 W LDGs in flight)
// for 8 chunks. BUILD: assemble [pe | chunk_emb] input tile in SMEM directly.
// EMITB: layer-3 epilogue writes permuted fp16 B image for the big GEMM.
template <int IND, bool RELU, bool EMITB, bool BUILD>
__global__ __launch_bounds__(512)
void layer_kernel(const float* __restrict__ in, const float* __restrict__ W,
                  const float* __restrict__ bias, float* __restrict__ out,
                  const float* __restrict__ preference,
                  const float* __restrict__ pref_emb,
                  const float* __restrict__ chunk_emb) {
    constexpr int Q = IND / 4;
    __shared__ float4 in_s[8][Q];
    __shared__ float pe[64];

    int tid = threadIdx.x, lane = tid & 31, warp = tid >> 5;
    int cbase = blockIdx.y * 8;

    if (BUILD) {
        if (tid < 64)
            pe[tid] = preference[0] * pref_emb[tid] +
                      preference[1] * pref_emb[64 + tid];
        __syncthreads();
        // Q == 32 here; item = (c, q): q<16 -> pe, else chunk_emb[c][q-16]
        for (int i = tid; i < 8 * Q; i += 512) {
            int c = i >> 5, q = i & 31;
            float4 v = make_float4(0.f, 0.f, 0.f, 0.f);
            if (cbase + c < NCHUNK) {
                if (q < 16)
                    v = reinterpret_cast<const float4*>(pe)[q];
                else
                    v = reinterpret_cast<const float4*>(chunk_emb)
                            [(cbase + c) * 16 + (q - 16)];
            }
            in_s[c][q] = v;
        }
    } else {
        for (int i = tid; i < 8 * Q; i += 512) {
            int c = i / Q, q = i % Q;
            float4 v = make_float4(0.f, 0.f, 0.f, 0.f);
            if (cbase + c < NCHUNK)
                v = reinterpret_cast<const float4*>(in)[(cbase + c) * Q + q];
            in_s[c][q] = v;
        }
    }
    __syncthreads();

    int j0 = blockIdx.x * 32 + warp * 2;
    int j1 = j0 + 1;
    const float4* W0 = reinterpret_cast<const float4*>(W) + (size_t)j0 * Q;
    const float4* W1r = reinterpret_cast<const float4*>(W) + (size_t)j1 * Q;

    float acc0[8], acc1[8];
#pragma unroll
    for (int c = 0; c < 8; c++) { acc0[c] = 0.f; acc1[c] = 0.f; }

#pragma unroll
    for (int ii = 0; ii < Q; ii += 32) {
        float4 w0 = W0[lane + ii];
        float4 w1 = W1r[lane + ii];
#pragma unroll
        for (int c = 0; c < 8; c++) {
            float4 x = in_s[c][lane + ii];
            acc0[c] += dot4(w0, x);
            acc1[c] += dot4(w1, x);
        }
    }

    float bj0 = 0.f, bj1 = 0.f;
    if (lane == 0) { bj0 = bias[j0]; bj1 = bias[j1]; }

    int aa0 = j0 & 15, aa1 = j1 & 15;
    int row0 = (j0 >> 4) * 8 + (aa0 >> 2) + 4 * ((aa0 >> 1) & 1);
    int row1 = (j1 >> 4) * 8 + (aa1 >> 2) + 4 * ((aa1 >> 1) & 1);
    int bs0 = aa0 & 1, bs1 = aa1 & 1;

#pragma unroll
    for (int c = 0; c < 8; c++) {
        float v0 = acc0[c], v1 = acc1[c];
#pragma unroll
        for (int off = 16; off; off >>= 1) {
            v0 += __shfl_down_sync(~0u, v0, off);
            v1 += __shfl_down_sync(~0u, v1, off);
        }
        if (lane == 0 && (cbase + c) < NCHUNK) {
            v0 += bj0; v1 += bj1;
            if (RELU) { v0 = fmaxf(v0, 0.f); v1 = fmaxf(v1, 0.f); }
            if (EMITB) {
                g_Bp[row0 * 224 + (cbase + c) * 2 + bs0] = __float2half_rn(v0);
                g_Bp[row1 * 224 + (cbase + c) * 2 + bs1] = __float2half_rn(v1);
            } else {
                out[(cbase + c) * HID + j0] = v0;
                out[(cbase + c) * HID + j1] = v1;
            }
        }
    }
}

// ---------------- big GEMM: out[n][m] = ws[m] . rep[n] -------------------
// (UNCHANGED from R13: 8 warps, m32 x n112, direct LDG, 4-deep prefetch.)
__global__ __launch_bounds__(256, 1)
void big_kernel(const float* __restrict__ ws, float* __restrict__ out) {
    extern __shared__ char smem[];
    const uint32_t sb = smem_u32_of(smem);
    const int tid = threadIdx.x, lane = tid & 31, wid = tid >> 5;

    // load permuted B image (256 rows x 224 halves) with 480B row stride
    {
        const float4* src = reinterpret_cast<const float4*>(g_Bp);
        for (int i = tid; i < 256 * 28; i += 256) {
            int r = i / 28, q = i - r * 28;
            *reinterpret_cast<float4*>(smem + r * BSROW + q * 16) = src[i];
        }
    }
    __syncthreads();

    const int g = lane >> 2, q = lane & 3;
    const long long mwbase = (long long)blockIdx.x * MT + wid * 32;

    const float4* ap[4];
#pragma unroll
    for (int j = 0; j < 4; j++) {
        long long r = mwbase + g + 8 * j;
        if (r >= NROWS) r = NROWS - 1;
        ap[j] = reinterpret_cast<const float4*>(ws) + r * (KD / 4) + q;
    }

    const uint32_t bbase = sb + (uint32_t)(lane & 3) * BSROW + (uint32_t)(lane >> 2) * 4;

    float acc[2][NTILES][4];
#pragma unroll
    for (int a = 0; a < 2; a++)
#pragma unroll
        for (int b = 0; b < NTILES; b++)
#pragma unroll
            for (int c = 0; c < 4; c++) acc[a][b][c] = 0.f;

    // 4-deep A prefetch
    float4 pa[4][4];
#pragma unroll
    for (int j = 0; j < 4; j++) {
#pragma unroll
        for (int d = 0; d < 4; d++) pa[j][d] = ap[j][d * 4];
    }

#pragma unroll 4
    for (int t = 0; t < KSTEPS; t++) {
        float4 ca[4];
#pragma unroll
        for (int j = 0; j < 4; j++) {
            ca[j] = pa[j][t & 3];
            if (t + 4 < KSTEPS) pa[j][t & 3] = ap[j][(t + 4) * 4];
        }
        uint32_t ar[2][4];
        ar[0][0] = cvt2(ca[0].x, ca[0].y);
        ar[0][1] = cvt2(ca[1].x, ca[1].y);
        ar[0][2] = cvt2(ca[0].z, ca[0].w);
        ar[0][3] = cvt2(ca[1].z, ca[1].w);
        ar[1][0] = cvt2(ca[2].x, ca[2].y);
        ar[1][1] = cvt2(ca[3].x, ca[3].y);
        ar[1][2] = cvt2(ca[2].z, ca[2].w);
        ar[1][3] = cvt2(ca[3].z, ca[3].w);

        uint32_t brow = bbase + (uint32_t)t * (8 * BSROW);
#pragma unroll
        for (int nt = 0; nt < NTILES; nt++) {
            uint32_t bfr[2];
            bfr[0] = ldsb32(brow + nt * 32);
            bfr[1] = ldsb32(brow + 4 * BSROW + nt * 32);
            mma16816(acc[0][nt], ar[0], bfr);
            mma16816(acc[1][nt], ar[1], bfr);
        }
    }

    // ---- epilogue ----
#pragma unroll
    for (int tm = 0; tm < 2; tm++) {
        long long m0 = mwbase + tm * 16 + g;
        long long m1 = m0 + 8;
        int nb = 2 * q;
#pragma unroll
        for (int nt = 0; nt < NTILES; nt++) {
            int n0 = nt * 8 + nb, n1 = n0 + 1;
            const float* c = acc[tm][nt];
            if (m0 < NROWS) {
                if (n0 < NCHUNK) out[(size_t)n0 * NROWS + m0] = c[0];
                if (n1 < NCHUNK) out[(size_t)n1 * NROWS + m0] = c[1];
            }
            if (m1 < NROWS) {
                if (n0 < NCHUNK) out[(size_t)n0 * NROWS + m1] = c[2];
                if (n1 < NCHUNK) out[(size_t)n1 * NROWS + m1] = c[3];
            }
        }
    }
}

// ---------------------------- launcher -----------------------------------
extern "C" void kernel_launch(void* const* d_in, const int* in_sizes, int n_in,
                              void* d_out, int out_size) {
    const float* preference = (const float*)d_in[0];
    const float* pref_emb   = (const float*)d_in[1];
    const float* chunk_emb  = (const float*)d_in[2];
    const float* W1         = (const float*)d_in[3];
    const float* b1         = (const float*)d_in[4];
    const float* W2         = (const float*)d_in[5];
    const float* b2         = (const float*)d_in[6];
    const float* W3         = (const float*)d_in[7];
    const float* b3         = (const float*)d_in[8];
    const float* ws         = (const float*)d_in[9];
    float* out = (float*)d_out;

    float *ph1, *ph2;
    cudaGetSymbolAddress((void**)&ph1, g_h1);
    cudaGetSymbolAddress((void**)&ph2, g_h2);

    static int attr_done = 0;
    if (!attr_done) {
        cudaFuncSetAttribute(big_kernel,
            cudaFuncAttributeMaxDynamicSharedMemorySize, BS_SMEM);
        attr_done = 1;
    }

    dim3 lgrid(HID / 32, (NCHUNK + 7) / 8);  // 16 x 14
    layer_kernel<IND1, true,  false, true ><<<lgrid, 512>>>(
        nullptr, W1, b1, ph1, preference, pref_emb, chunk_emb);
    layer_kernel<HID,  true,  false, false><<<lgrid, 512>>>(
        ph1, W2, b2, ph2, nullptr, nullptr, nullptr);
    layer_kernel<HID,  false, true,  false><<<lgrid, 512>>>(
        ph2, W3, b3, nullptr, nullptr, nullptr, nullptr);

    int nblocks = (NROWS + MT - 1) / MT;   // 860
    big_kernel<<<nblocks, 256, BS_SMEM>>>(ws, out);
}